// round 7
// baseline (speedup 1.0000x reference)
#include <cuda_runtime.h>
#include <cstdint>

#define NPTS 16384
#define NDIM 64
#define NB   8
#define NSEG (NB * NDIM)
#define EPSF 0.1f
#define MINS 5
#define NCMAX 512
#define FULLM 0xffffffffu
#define NSM 148

// ---------------- global scratch ----------------
__device__ float    g_xt[(size_t)NB * NDIM * NPTS];
__device__ short    g_lab[(size_t)NB * NDIM * NPTS];
__device__ int      g_ncl[NSEG];
__device__ int      g_off[NSEG];
__device__ unsigned g_ctr;

extern __shared__ unsigned char dsm[];

// ---------------- kernel 0: transpose (B,N,D) -> (B,D,N) ----------------
__global__ void transpose_kernel(const float* __restrict__ f) {
    __shared__ float tile[64][65];
    if (blockIdx.x == 0 && threadIdx.x == 0) g_ctr = 0u;
    int b  = blockIdx.x >> 8;
    int n0 = (blockIdx.x & 255) << 6;
    int tid = threadIdx.x;
    const float* src = f + ((size_t)b * NPTS + n0) * NDIM;
    #pragma unroll
    for (int idx = tid; idx < 64 * 64; idx += 256) {
        int n = idx >> 6, d = idx & 63;
        tile[n][d] = src[idx];
    }
    __syncthreads();
    #pragma unroll
    for (int idx = tid; idx < 64 * 64; idx += 256) {
        int d = idx >> 6, n = idx & 63;
        g_xt[(((size_t)b * NDIM + d) << 14) + n0 + n] = tile[n][d];
    }
}

// ---------------- block scan helpers (1024 threads) ----------------
__device__ __forceinline__ int blkscan_excl_add(int v, int* aux) {
    int lane = threadIdx.x & 31, wid = threadIdx.x >> 5;
    int incl = v;
    #pragma unroll
    for (int o = 1; o < 32; o <<= 1) {
        int u = __shfl_up_sync(FULLM, incl, o);
        if (lane >= o) incl += u;
    }
    if (lane == 31) aux[wid] = incl;
    __syncthreads();
    if (wid == 0) {
        int w = aux[lane];
        #pragma unroll
        for (int o = 1; o < 32; o <<= 1) {
            int u = __shfl_up_sync(FULLM, w, o);
            if (lane >= o) w += u;
        }
        aux[lane] = w;
    }
    __syncthreads();
    int wex = __shfl_up_sync(FULLM, incl, 1);
    if (lane == 0) wex = 0;
    int pre = (wid > 0) ? (wex + aux[wid - 1]) : wex;
    __syncthreads();
    return pre;
}

__device__ __forceinline__ int blkscan_excl_max(int v, int* aux) {
    int lane = threadIdx.x & 31, wid = threadIdx.x >> 5;
    int incl = v;
    #pragma unroll
    for (int o = 1; o < 32; o <<= 1) {
        int u = __shfl_up_sync(FULLM, incl, o);
        if (lane >= o) incl = max(incl, u);
    }
    if (lane == 31) aux[wid] = incl;
    __syncthreads();
    if (wid == 0) {
        int w = aux[lane];
        #pragma unroll
        for (int o = 1; o < 32; o <<= 1) {
            int u = __shfl_up_sync(FULLM, w, o);
            if (lane >= o) w = max(w, u);
        }
        aux[lane] = w;
    }
    __syncthreads();
    int wex = __shfl_up_sync(FULLM, incl, 1);
    if (lane == 0) wex = -1;
    int pre = (wid > 0) ? max(wex, aux[wid - 1]) : wex;
    __syncthreads();
    return pre;
}

__device__ __forceinline__ int blkscan_excl_min_suffix(int v, int* aux) {
    int lane = threadIdx.x & 31, wid = threadIdx.x >> 5;
    int incl = v;
    #pragma unroll
    for (int o = 1; o < 32; o <<= 1) {
        int u = __shfl_down_sync(FULLM, incl, o);
        if (lane < 32 - o) incl = min(incl, u);
    }
    if (lane == 0) aux[wid] = incl;
    __syncthreads();
    if (wid == 0) {
        int w = aux[lane];
        #pragma unroll
        for (int o = 1; o < 32; o <<= 1) {
            int u = __shfl_down_sync(FULLM, w, o);
            if (lane < 32 - o) w = min(w, u);
        }
        aux[lane] = w;
    }
    __syncthreads();
    int wex = __shfl_down_sync(FULLM, incl, 1);
    if (lane == 31) wex = NPTS;
    int pre = (wid < 31) ? min(wex, aux[wid + 1]) : wex;
    __syncthreads();
    return pre;
}

// ---------------- kernel 1: persistent per-(b,d) 1D DBSCAN ----------------
// smem layout (bytes):
//   [0,      65536)  u32 k0  -> float xs
//   [65536,  98304)  u16 p0  -> ordv
//   [98304, 163840)  u32 k1  ; s16 lastc @98304, s16 nextc @131072
//   [163840,196608)  u16 p1  -> s16 cidv
//   [196608,230400)  u16 wh[256][66] (bin-major, cols 0..63 used)  -> u8 corev
//   [230400,231424)  u16 chks[256][2]
//   [231424,231552)  i32 aux[32]
//   [231552,231556)  i32 s_bd
#define OFF_P0   65536
#define OFF_K1   98304
#define OFF_P1   163840
#define OFF_WH   196608
#define OFF_CH   230400
#define OFF_AUX  231424
#define OFF_SBD  231552
#define SMEM_BYTES 231556
#define WHSTRIDE 66

__global__ void __launch_bounds__(1024, 1) dbscan_kernel() {
    uint32_t* k0    = (uint32_t*)dsm;
    uint16_t* p0    = (uint16_t*)(dsm + OFF_P0);
    uint32_t* k1    = (uint32_t*)(dsm + OFF_K1);
    uint16_t* p1    = (uint16_t*)(dsm + OFF_P1);
    uint16_t* wh    = (uint16_t*)(dsm + OFF_WH);
    uint16_t* chks  = (uint16_t*)(dsm + OFF_CH);
    int*      aux   = (int*)(dsm + OFF_AUX);
    int*      s_bd  = (int*)(dsm + OFF_SBD);

    float*          xs    = (float*)dsm;
    uint16_t*       ordv  = p0;
    short*          lastc = (short*)(dsm + OFF_K1);
    short*          nextc = (short*)(dsm + 131072);
    short*          cidv  = (short*)(dsm + OFF_P1);
    unsigned char*  corev = (unsigned char*)(dsm + OFF_WH);

    int tid  = threadIdx.x;
    int lane = tid & 31;
    int wid  = tid >> 5;
    unsigned mask_lt = (1u << lane) - 1u;
    int ibase = (wid << 9) + lane;       // warp-major: item = ibase + q*32
    int base  = tid << 4;                // for phases 3..7 (16 consecutive)
    int colA  = (wid << 1);              // per-warp columns: stream A, B
    int colB  = colA + 1;

    for (;;) {
        if (tid == 0) *s_bd = (int)atomicAdd(&g_ctr, 1u);
        __syncthreads();
        int bd = *s_bd;
        if (bd >= NSEG) return;
        const float* x = g_xt + ((size_t)bd << 14);

        // phase 0: order-preserving keys + index payload (coalesced gmem reads)
        #pragma unroll 4
        for (int q = 0; q < 16; q++) {
            int i = ibase + (q << 5);
            unsigned u = __float_as_uint(x[i]);
            unsigned s = (u & 0x80000000u) ? ~u : (u | 0x80000000u);
            k0[i] = s;
            p0[i] = (uint16_t)i;
        }
        __syncthreads();

        // phase 1: 4-pass 8-bit LSD radix sort, STABLE, dual-stream ranking.
        // Stability: within each bin, allocation order = column asc =
        // (warp asc, stream A then B); stream A covers the warp's items
        // q=0..7 (lower indices), B covers q=8..15; within a stream the
        // (jj, lane) rank order equals memory (q, lane) order.
        uint32_t* kcur = k0; uint16_t* pcur = p0;
        uint32_t* kalt = k1; uint16_t* palt = p1;
        for (int pass = 0; pass < 4; pass++) {
            int shift = pass << 3;
            bool last = (pass == 3);

            // zero wh (33792 B = 8448 u32 words)
            for (int j = tid; j < 8448; j += 1024) ((uint32_t*)wh)[j] = 0;
            __syncthreads();

            // ---- histogram: dual-stream leader RMW ----
            #pragma unroll
            for (int jj = 0; jj < 8; jj++) {
                unsigned dA = (kcur[ibase + (jj << 5)] >> shift) & 255u;
                unsigned mA = __match_any_sync(FULLM, dA);
                if ((mA & mask_lt) == 0) {
                    int a = dA * WHSTRIDE + colA;
                    wh[a] = (uint16_t)(wh[a] + __popc(mA));
                }
                unsigned dB = (kcur[ibase + ((jj + 8) << 5)] >> shift) & 255u;
                unsigned mB = __match_any_sync(FULLM, dB);
                if ((mB & mask_lt) == 0) {
                    int a = dB * WHSTRIDE + colB;
                    wh[a] = (uint16_t)(wh[a] + __popc(mB));
                }
                __syncwarp();
            }
            __syncthreads();

            // ---- stage 1: per-(bin,half) partial sums (512 threads) ----
            // half 0 = columns 0..31, half 1 = columns 32..63 (column asc order)
            if (tid < 512) {
                int bin = tid >> 1, half = tid & 1;
                int a0 = bin * WHSTRIDE + (half << 5);
                int s = 0;
                #pragma unroll 8
                for (int r = 0; r < 32; r++) s += (int)wh[a0 + r];
                chks[(bin << 1) + half] = (uint16_t)s;
            }
            __syncthreads();

            // ---- stage 2: 256-bin exclusive scan -> per-half bases ----
            {
                int v = 0, c0 = 0;
                if (tid < 256) {
                    c0 = (int)chks[tid << 1];
                    v  = c0 + (int)chks[(tid << 1) + 1];
                }
                int incl = v;
                #pragma unroll
                for (int o = 1; o < 32; o <<= 1) {
                    int u = __shfl_up_sync(FULLM, incl, o);
                    if (lane >= o) incl += u;
                }
                if (tid < 256 && lane == 31) aux[wid] = incl;
                __syncthreads();
                if (tid == 0) {
                    int r = 0;
                    #pragma unroll
                    for (int w2 = 0; w2 < 8; w2++) { int c = aux[w2]; aux[w2] = r; r += c; }
                }
                __syncthreads();
                if (tid < 256) {
                    int excl = incl - v + aux[wid];
                    chks[tid << 1]       = (uint16_t)excl;
                    chks[(tid << 1) + 1] = (uint16_t)(excl + c0);
                }
            }
            __syncthreads();

            // ---- stage 3: write absolute bases back (column asc within half) ----
            if (tid < 512) {
                int bin = tid >> 1, half = tid & 1;
                int a0 = bin * WHSTRIDE + (half << 5);
                int run = (int)chks[(bin << 1) + half];
                #pragma unroll 8
                for (int r = 0; r < 32; r++) {
                    int c = (int)wh[a0 + r];
                    wh[a0 + r] = (uint16_t)run;
                    run += c;
                }
            }
            __syncthreads();

            // ---- rank & scatter (dual-stream, one syncwarp per pair) ----
            #pragma unroll
            for (int jj = 0; jj < 8; jj++) {
                // stream A: item q=jj
                {
                    int i = ibase + (jj << 5);
                    unsigned k = kcur[i];
                    uint16_t pl = pcur[i];
                    unsigned d = (k >> shift) & 255u;
                    unsigned m = __match_any_sync(FULLM, d);
                    int ldr = __ffs(m) - 1;
                    int off = __popc(m & mask_lt);
                    int b2 = 0;
                    if (off == 0) {
                        int a = d * WHSTRIDE + colA;
                        b2 = (int)wh[a];
                        wh[a] = (uint16_t)(b2 + __popc(m));
                    }
                    b2 = __shfl_sync(FULLM, b2, ldr);
                    int dst = b2 + off;
                    if (last) {
                        unsigned u = (k & 0x80000000u) ? (k & 0x7fffffffu) : ~k;
                        kalt[dst] = u;
                    } else kalt[dst] = k;
                    palt[dst] = pl;
                }
                // stream B: item q=jj+8
                {
                    int i = ibase + ((jj + 8) << 5);
                    unsigned k = kcur[i];
                    uint16_t pl = pcur[i];
                    unsigned d = (k >> shift) & 255u;
                    unsigned m = __match_any_sync(FULLM, d);
                    int ldr = __ffs(m) - 1;
                    int off = __popc(m & mask_lt);
                    int b2 = 0;
                    if (off == 0) {
                        int a = d * WHSTRIDE + colB;
                        b2 = (int)wh[a];
                        wh[a] = (uint16_t)(b2 + __popc(m));
                    }
                    b2 = __shfl_sync(FULLM, b2, ldr);
                    int dst = b2 + off;
                    if (last) {
                        unsigned u = (k & 0x80000000u) ? (k & 0x7fffffffu) : ~k;
                        kalt[dst] = u;
                    } else kalt[dst] = k;
                    palt[dst] = pl;
                }
                __syncwarp();
            }
            __syncthreads();
            uint32_t* tk = kcur; kcur = kalt; kalt = tk;
            uint16_t* tp = pcur; pcur = palt; palt = tp;
        }
        // sorted float bits now in k0 (=xs), payload in p0 (=ordv)

        // phase 3: core test — 2 binary searches per thread + monotone advance
        {
            float v0 = xs[base];
            float tU = v0 + EPSF, tL = v0 - EPSF;
            int lo = 0, hi = NPTS;
            while (lo < hi) { int m = (lo + hi) >> 1; if (xs[m] <= tU) lo = m + 1; else hi = m; }
            int phi = lo;
            lo = 0; hi = NPTS;
            while (lo < hi) { int m = (lo + hi) >> 1; if (xs[m] <  tL) lo = m + 1; else hi = m; }
            int plo = lo;
            corev[base] = (unsigned char)((phi - plo) >= MINS);
            #pragma unroll 1
            for (int q = 1; q < 16; q++) {
                float v = xs[base + q];
                float u2 = v + EPSF, l2 = v - EPSF;
                while (phi < NPTS && xs[phi] <= u2) phi++;
                while (plo < NPTS && xs[plo] <  l2) plo++;
                corev[base + q] = (unsigned char)((phi - plo) >= MINS);
            }
        }
        __syncthreads();

        // phase 4: forward inclusive max (core ? i : -1) -> nearest left core
        {
            int run = -1;
            #pragma unroll 4
            for (int q = 0; q < 16; q++) {
                int i = base + q;
                int v = corev[i] ? i : -1;
                if (v > run) run = v;
                lastc[i] = (short)run;
            }
            int pre = blkscan_excl_max(run, aux);
            #pragma unroll 4
            for (int q = 0; q < 16; q++) {
                int i = base + q;
                int c = (int)lastc[i];
                if (pre > c) lastc[i] = (short)pre;
            }
        }
        __syncthreads();

        // phase 5: new_cluster + cumsum -> cid
        {
            int run = 0;
            #pragma unroll 4
            for (int q = 0; q < 16; q++) {
                int i = base + q;
                int p = (i == 0) ? -1 : (int)lastc[i - 1];
                float pv = (p >= 0) ? xs[p] : -INFINITY;
                int nc = (corev[i] && ((xs[i] - pv) > EPSF)) ? 1 : 0;
                run += nc;
                cidv[i] = (short)run;
            }
            int pre = blkscan_excl_add(run, aux);
            #pragma unroll 4
            for (int q = 0; q < 16; q++) {
                int i = base + q;
                cidv[i] = (short)((int)cidv[i] + pre - 1);
            }
        }
        __syncthreads();

        // phase 6: backward inclusive min (core ? i : NPTS) -> nearest right core
        {
            int run = NPTS;
            #pragma unroll 4
            for (int q = 15; q >= 0; q--) {
                int i = base + q;
                int v = corev[i] ? i : NPTS;
                if (v < run) run = v;
                nextc[i] = (short)run;
            }
            int pre = blkscan_excl_min_suffix(run, aux);
            #pragma unroll 4
            for (int q = 0; q < 16; q++) {
                int i = base + q;
                int v = (int)nextc[i];
                if (pre < v) nextc[i] = (short)pre;
            }
        }
        __syncthreads();

        // phase 7: labels -> unsort to g_lab; write ncl
        #pragma unroll 2
        for (int q = 0; q < 16; q++) {
            int i = base + q;
            int lab;
            if (corev[i]) {
                lab = (int)cidv[i];
            } else {
                int lc = (int)lastc[i], rc = (int)nextc[i];
                float lv = (lc >= 0)   ? xs[lc] : -INFINITY;
                float rv = (rc < NPTS) ? xs[rc] :  INFINITY;
                float dl = xs[i] - lv;
                float dr = rv - xs[i];
                float mn = dl < dr ? dl : dr;
                if (mn <= EPSF) lab = (dl <= dr) ? (int)cidv[lc] : (int)cidv[rc];
                else            lab = -1;
            }
            g_lab[((size_t)bd << 14) + ordv[i]] = (short)lab;
            if (i == NPTS - 1) g_ncl[bd] = (int)cidv[i] + 1;
        }
        __syncthreads();
    }
}

// ---------------- kernel 2: offsets ----------------
__global__ void offsets_kernel() {
    __shared__ int s[NSEG];
    int t = threadIdx.x;
    s[t] = g_ncl[t];
    __syncthreads();
    int b = t >> 6, d = t & 63;
    int off = 0;
    for (int j = 0; j < d; j++) off += s[(b << 6) + j];
    g_off[t] = off;
}

// ---------------- kernel 3: fused zero + scatter ----------------
__global__ void scatter_kernel(float* __restrict__ out) {
    __shared__ short labs[64 * 128];
    __shared__ int   offs[64];
    int b  = blockIdx.x >> 7;
    int n0 = (blockIdx.x & 127) << 7;
    int tid = threadIdx.x;
    if (tid < 64) offs[tid] = g_off[(b << 6) + tid];
    for (int idx = tid; idx < 64 * 128; idx += 256) {
        int d = idx >> 7, n = idx & 127;
        labs[idx] = g_lab[(((size_t)(b * NDIM + d)) << 14) + n0 + n];
    }
    __syncthreads();
    float* o = out + (((size_t)b * NPTS) + n0) * NCMAX;
    float4* o4 = (float4*)o;
    float4 z = make_float4(0.f, 0.f, 0.f, 0.f);
    for (int idx = tid; idx < 128 * NCMAX / 4; idx += 256) o4[idx] = z;
    __syncthreads();
    for (int idx = tid; idx < 128 * 64; idx += 256) {
        int n = idx >> 6, d = idx & 63;
        int lab = (int)labs[d * 128 + n];
        if (lab >= 0) {
            int g = lab + offs[d];
            if (g < NCMAX) o[(size_t)n * NCMAX + g] = 1.0f;
        }
    }
}

// ---------------- entry point ----------------
extern "C" void kernel_launch(void* const* d_in, const int* in_sizes, int n_in,
                              void* d_out, int out_size) {
    (void)in_sizes; (void)n_in; (void)out_size;
    const float* f = (const float*)d_in[0];

    cudaFuncSetAttribute(dbscan_kernel,
                         cudaFuncAttributeMaxDynamicSharedMemorySize, SMEM_BYTES);

    transpose_kernel<<<NB * (NPTS / 64), 256>>>(f);
    dbscan_kernel<<<NSM, 1024, SMEM_BYTES>>>();
    offsets_kernel<<<1, NSEG>>>();
    scatter_kernel<<<NB * (NPTS / 128), 256>>>((float*)d_out);
}

// round 8
// speedup vs baseline: 1.9275x; 1.9275x over previous
#include <cuda_runtime.h>
#include <cstdint>

#define NPTS 16384
#define NDIM 64
#define NB   8
#define NSEG (NB * NDIM)
#define EPSF 0.1f
#define MINS 5
#define NCMAX 512
#define FULLM 0xffffffffu
#define NSM 148
#define NBINS 16384

// ---------------- global scratch ----------------
__device__ float    g_xt[(size_t)NB * NDIM * NPTS];
__device__ short    g_lab[(size_t)NB * NDIM * NPTS];
__device__ int      g_ncl[NSEG];
__device__ int      g_off[NSEG];
__device__ unsigned g_ctr;

extern __shared__ unsigned char dsm[];

// ---------------- kernel 0: transpose (B,N,D) -> (B,D,N) ----------------
__global__ void transpose_kernel(const float* __restrict__ f) {
    __shared__ float tile[64][65];
    if (blockIdx.x == 0 && threadIdx.x == 0) g_ctr = 0u;
    int b  = blockIdx.x >> 8;
    int n0 = (blockIdx.x & 255) << 6;
    int tid = threadIdx.x;
    const float* src = f + ((size_t)b * NPTS + n0) * NDIM;
    #pragma unroll
    for (int idx = tid; idx < 64 * 64; idx += 256) {
        int n = idx >> 6, d = idx & 63;
        tile[n][d] = src[idx];
    }
    __syncthreads();
    #pragma unroll
    for (int idx = tid; idx < 64 * 64; idx += 256) {
        int d = idx >> 6, n = idx & 63;
        g_xt[(((size_t)b * NDIM + d) << 14) + n0 + n] = tile[n][d];
    }
}

// ---------------- block scan helpers (1024 threads) ----------------
__device__ __forceinline__ int blkscan_excl_add(int v, int* aux) {
    int lane = threadIdx.x & 31, wid = threadIdx.x >> 5;
    int incl = v;
    #pragma unroll
    for (int o = 1; o < 32; o <<= 1) {
        int u = __shfl_up_sync(FULLM, incl, o);
        if (lane >= o) incl += u;
    }
    if (lane == 31) aux[wid] = incl;
    __syncthreads();
    if (wid == 0) {
        int w = aux[lane];
        #pragma unroll
        for (int o = 1; o < 32; o <<= 1) {
            int u = __shfl_up_sync(FULLM, w, o);
            if (lane >= o) w += u;
        }
        aux[lane] = w;
    }
    __syncthreads();
    int wex = __shfl_up_sync(FULLM, incl, 1);
    if (lane == 0) wex = 0;
    int pre = (wid > 0) ? (wex + aux[wid - 1]) : wex;
    __syncthreads();
    return pre;
}

__device__ __forceinline__ int blkscan_excl_max(int v, int* aux) {
    int lane = threadIdx.x & 31, wid = threadIdx.x >> 5;
    int incl = v;
    #pragma unroll
    for (int o = 1; o < 32; o <<= 1) {
        int u = __shfl_up_sync(FULLM, incl, o);
        if (lane >= o) incl = max(incl, u);
    }
    if (lane == 31) aux[wid] = incl;
    __syncthreads();
    if (wid == 0) {
        int w = aux[lane];
        #pragma unroll
        for (int o = 1; o < 32; o <<= 1) {
            int u = __shfl_up_sync(FULLM, w, o);
            if (lane >= o) w = max(w, u);
        }
        aux[lane] = w;
    }
    __syncthreads();
    int wex = __shfl_up_sync(FULLM, incl, 1);
    if (lane == 0) wex = -1;
    int pre = (wid > 0) ? max(wex, aux[wid - 1]) : wex;
    __syncthreads();
    return pre;
}

__device__ __forceinline__ int blkscan_excl_min_suffix(int v, int* aux) {
    int lane = threadIdx.x & 31, wid = threadIdx.x >> 5;
    int incl = v;
    #pragma unroll
    for (int o = 1; o < 32; o <<= 1) {
        int u = __shfl_down_sync(FULLM, incl, o);
        if (lane < 32 - o) incl = min(incl, u);
    }
    if (lane == 0) aux[wid] = incl;
    __syncthreads();
    if (wid == 0) {
        int w = aux[lane];
        #pragma unroll
        for (int o = 1; o < 32; o <<= 1) {
            int u = __shfl_down_sync(FULLM, w, o);
            if (lane < 32 - o) w = min(w, u);
        }
        aux[lane] = w;
    }
    __syncthreads();
    int wex = __shfl_down_sync(FULLM, incl, 1);
    if (lane == 31) wex = NPTS;
    int pre = (wid < 31) ? min(wex, aux[wid + 1]) : wex;
    __syncthreads();
    return pre;
}

// ---------------- kernel 1: persistent per-(b,d) 1D DBSCAN (bin-sort based) ----------------
// smem layout (bytes):
//   [0,      65536)  float xs[16384]                (sorted values)
//   [65536,  98304)  u16  ordv[16384]               (original index)
//   [98304, 131072)  u32  histp[8192] (2x u16)      -> s16 lastc after sort
//   [131072,163840)  u32  curp[8192]  (2x u16)      -> s16 nextc after cleanup
//   [163840,196608)  u16  boff[16384]               -> s16 cidv after cleanup
//   [196608,212992)  u8   corev[16384]
//   [212992,213120)  i32  aux[32]
//   [213120,213248)  f32  redmn[32]
//   [213248,213376)  f32  redmx[32]
//   [213376,213388)  s_bd, s_mn, s_mx
#define OFF_ORD  65536
#define OFF_HIST 98304
#define OFF_CUR  131072
#define OFF_BOFF 163840
#define OFF_CORE 196608
#define OFF_AUX  212992
#define OFF_REDN 213120
#define OFF_REDX 213248
#define OFF_SBD  213376
#define OFF_SMN  213380
#define OFF_SMX  213384
#define SMEM_BYTES 213388

__global__ void __launch_bounds__(1024, 1) dbscan_kernel() {
    float*          xs    = (float*)dsm;
    uint16_t*       ordv  = (uint16_t*)(dsm + OFF_ORD);
    uint32_t*       histp = (uint32_t*)(dsm + OFF_HIST);
    uint32_t*       curp  = (uint32_t*)(dsm + OFF_CUR);
    uint16_t*       boff  = (uint16_t*)(dsm + OFF_BOFF);
    unsigned char*  corev = (unsigned char*)(dsm + OFF_CORE);
    int*            aux   = (int*)(dsm + OFF_AUX);
    float*          redmn = (float*)(dsm + OFF_REDN);
    float*          redmx = (float*)(dsm + OFF_REDX);
    int*            s_bd  = (int*)(dsm + OFF_SBD);
    float*          s_mn  = (float*)(dsm + OFF_SMN);
    float*          s_mx  = (float*)(dsm + OFF_SMX);

    short* lastc = (short*)(dsm + OFF_HIST);
    short* nextc = (short*)(dsm + OFF_CUR);
    short* cidv  = (short*)(dsm + OFF_BOFF);

    int tid  = threadIdx.x;
    int lane = tid & 31;
    int wid  = tid >> 5;
    int base = tid << 4;

    for (;;) {
        if (tid == 0) *s_bd = (int)atomicAdd(&g_ctr, 1u);
        __syncthreads();
        int bd = *s_bd;
        if (bd >= NSEG) return;
        const float* x = g_xt + ((size_t)bd << 14);

        // ---- load 16 values into registers (coalesced) ----
        float v[16];
        #pragma unroll
        for (int q = 0; q < 16; q++) v[q] = x[tid + (q << 10)];

        // ---- block min/max ----
        float mn = v[0], mx = v[0];
        #pragma unroll
        for (int q = 1; q < 16; q++) { mn = fminf(mn, v[q]); mx = fmaxf(mx, v[q]); }
        #pragma unroll
        for (int o = 16; o > 0; o >>= 1) {
            mn = fminf(mn, __shfl_xor_sync(FULLM, mn, o));
            mx = fmaxf(mx, __shfl_xor_sync(FULLM, mx, o));
        }
        if (lane == 0) { redmn[wid] = mn; redmx[wid] = mx; }
        __syncthreads();
        if (wid == 0) {
            mn = redmn[lane]; mx = redmx[lane];
            #pragma unroll
            for (int o = 16; o > 0; o >>= 1) {
                mn = fminf(mn, __shfl_xor_sync(FULLM, mn, o));
                mx = fmaxf(mx, __shfl_xor_sync(FULLM, mx, o));
            }
            if (lane == 0) { *s_mn = mn; *s_mx = mx; }
        }
        __syncthreads();
        mn = *s_mn;
        float range = *s_mx - mn;

        if (range > 0.0f) {                 // uniform branch (shared values)
            float scale = 16383.0f / range;

            // ---- histogram (packed 2x u16 per u32) ----
            #pragma unroll 4
            for (int w = tid; w < 8192; w += 1024) histp[w] = 0;
            __syncthreads();
            #pragma unroll
            for (int q = 0; q < 16; q++) {
                int b = (int)((v[q] - mn) * scale);
                b = min(b, NBINS - 1);
                atomicAdd(&histp[b >> 1], (b & 1) ? 65536u : 1u);
            }
            __syncthreads();

            // ---- prefix over 16384 bins (16 consecutive bins per thread) ----
            {
                int t16 = tid << 4;
                int cnt[16];
                #pragma unroll
                for (int j = 0; j < 8; j++) {
                    uint32_t w = histp[(t16 >> 1) + j];
                    cnt[2 * j]     = (int)(w & 0xffffu);
                    cnt[2 * j + 1] = (int)(w >> 16);
                }
                int tot = 0;
                #pragma unroll
                for (int q = 0; q < 16; q++) tot += cnt[q];
                int bs = blkscan_excl_add(tot, aux);
                #pragma unroll
                for (int q = 0; q < 16; q++) { boff[t16 + q] = (uint16_t)bs; bs += cnt[q]; }
            }
            __syncthreads();

            // ---- init packed cursors from boff ----
            #pragma unroll 4
            for (int w = tid; w < 8192; w += 1024)
                curp[w] = (uint32_t)boff[2 * w] | ((uint32_t)boff[2 * w + 1] << 16);
            __syncthreads();

            // ---- scatter (unstable within bin: ties have equal values) ----
            #pragma unroll
            for (int q = 0; q < 16; q++) {
                int b = (int)((v[q] - mn) * scale);
                b = min(b, NBINS - 1);
                uint32_t old = atomicAdd(&curp[b >> 1], (b & 1) ? 65536u : 1u);
                int dst = (b & 1) ? (int)(old >> 16) : (int)(old & 0xffffu);
                xs[dst]   = v[q];
                ordv[dst] = (uint16_t)(tid + (q << 10));
            }
            __syncthreads();

            // ---- cleanup: insertion-sort multi-element bins (interleaved map) ----
            #pragma unroll 1
            for (int k = 0; k < 16; k++) {
                int b  = tid + (k << 10);
                int lo = (int)boff[b];
                uint32_t cw = curp[b >> 1];
                int hi = (b & 1) ? (int)(cw >> 16) : (int)(cw & 0xffffu);
                for (int i2 = lo + 1; i2 < hi; i2++) {
                    float kv = xs[i2]; uint16_t pv = ordv[i2];
                    int j = i2 - 1;
                    while (j >= lo && xs[j] > kv) {
                        xs[j + 1] = xs[j]; ordv[j + 1] = ordv[j]; j--;
                    }
                    xs[j + 1] = kv; ordv[j + 1] = pv;
                }
            }
        } else {
            // all values equal -> already sorted
            #pragma unroll
            for (int q = 0; q < 16; q++) {
                int i = tid + (q << 10);
                xs[i] = v[q]; ordv[i] = (uint16_t)i;
            }
        }
        __syncthreads();

        // ---- phase 3: core test — 2 binary searches + monotone advance ----
        {
            float v0 = xs[base];
            float tU = v0 + EPSF, tL = v0 - EPSF;
            int lo = 0, hi = NPTS;
            while (lo < hi) { int m = (lo + hi) >> 1; if (xs[m] <= tU) lo = m + 1; else hi = m; }
            int phi = lo;
            lo = 0; hi = NPTS;
            while (lo < hi) { int m = (lo + hi) >> 1; if (xs[m] <  tL) lo = m + 1; else hi = m; }
            int plo = lo;
            corev[base] = (unsigned char)((phi - plo) >= MINS);
            #pragma unroll 1
            for (int q = 1; q < 16; q++) {
                float vv = xs[base + q];
                float u2 = vv + EPSF, l2 = vv - EPSF;
                while (phi < NPTS && xs[phi] <= u2) phi++;
                while (plo < NPTS && xs[plo] <  l2) plo++;
                corev[base + q] = (unsigned char)((phi - plo) >= MINS);
            }
        }
        __syncthreads();

        // ---- phase 4: forward inclusive max (core ? i : -1) -> nearest left core ----
        {
            int run = -1;
            #pragma unroll 4
            for (int q = 0; q < 16; q++) {
                int i = base + q;
                int vv = corev[i] ? i : -1;
                if (vv > run) run = vv;
                lastc[i] = (short)run;
            }
            int pre = blkscan_excl_max(run, aux);
            #pragma unroll 4
            for (int q = 0; q < 16; q++) {
                int i = base + q;
                int c = (int)lastc[i];
                if (pre > c) lastc[i] = (short)pre;
            }
        }
        __syncthreads();

        // ---- phase 5: new_cluster + cumsum -> cid ----
        {
            int run = 0;
            #pragma unroll 4
            for (int q = 0; q < 16; q++) {
                int i = base + q;
                int p = (i == 0) ? -1 : (int)lastc[i - 1];
                float pv = (p >= 0) ? xs[p] : -INFINITY;
                int nc = (corev[i] && ((xs[i] - pv) > EPSF)) ? 1 : 0;
                run += nc;
                cidv[i] = (short)run;
            }
            int pre = blkscan_excl_add(run, aux);
            #pragma unroll 4
            for (int q = 0; q < 16; q++) {
                int i = base + q;
                cidv[i] = (short)((int)cidv[i] + pre - 1);
            }
        }
        __syncthreads();

        // ---- phase 6: backward inclusive min (core ? i : NPTS) -> nearest right core ----
        {
            int run = NPTS;
            #pragma unroll 4
            for (int q = 15; q >= 0; q--) {
                int i = base + q;
                int vv = corev[i] ? i : NPTS;
                if (vv < run) run = vv;
                nextc[i] = (short)run;
            }
            int pre = blkscan_excl_min_suffix(run, aux);
            #pragma unroll 4
            for (int q = 0; q < 16; q++) {
                int i = base + q;
                int vv = (int)nextc[i];
                if (pre < vv) nextc[i] = (short)pre;
            }
        }
        __syncthreads();

        // ---- phase 7: labels -> unsort to g_lab; write ncl ----
        #pragma unroll 2
        for (int q = 0; q < 16; q++) {
            int i = base + q;
            int lab;
            if (corev[i]) {
                lab = (int)cidv[i];
            } else {
                int lc = (int)lastc[i], rc = (int)nextc[i];
                float lv = (lc >= 0)   ? xs[lc] : -INFINITY;
                float rv = (rc < NPTS) ? xs[rc] :  INFINITY;
                float dl = xs[i] - lv;
                float dr = rv - xs[i];
                float mmn = dl < dr ? dl : dr;
                if (mmn <= EPSF) lab = (dl <= dr) ? (int)cidv[lc] : (int)cidv[rc];
                else             lab = -1;
            }
            g_lab[((size_t)bd << 14) + ordv[i]] = (short)lab;
            if (i == NPTS - 1) g_ncl[bd] = (int)cidv[i] + 1;
        }
        __syncthreads();
    }
}

// ---------------- kernel 2: offsets ----------------
__global__ void offsets_kernel() {
    __shared__ int s[NSEG];
    int t = threadIdx.x;
    s[t] = g_ncl[t];
    __syncthreads();
    int b = t >> 6, d = t & 63;
    int off = 0;
    for (int j = 0; j < d; j++) off += s[(b << 6) + j];
    g_off[t] = off;
}

// ---------------- kernel 3: fused zero + scatter ----------------
__global__ void scatter_kernel(float* __restrict__ out) {
    __shared__ short labs[64 * 128];
    __shared__ int   offs[64];
    int b  = blockIdx.x >> 7;
    int n0 = (blockIdx.x & 127) << 7;
    int tid = threadIdx.x;
    if (tid < 64) offs[tid] = g_off[(b << 6) + tid];
    for (int idx = tid; idx < 64 * 128; idx += 256) {
        int d = idx >> 7, n = idx & 127;
        labs[idx] = g_lab[(((size_t)(b * NDIM + d)) << 14) + n0 + n];
    }
    __syncthreads();
    float* o = out + (((size_t)b * NPTS) + n0) * NCMAX;
    float4* o4 = (float4*)o;
    float4 z = make_float4(0.f, 0.f, 0.f, 0.f);
    for (int idx = tid; idx < 128 * NCMAX / 4; idx += 256) o4[idx] = z;
    __syncthreads();
    for (int idx = tid; idx < 128 * 64; idx += 256) {
        int n = idx >> 6, d = idx & 63;
        int lab = (int)labs[d * 128 + n];
        if (lab >= 0) {
            int g = lab + offs[d];
            if (g < NCMAX) o[(size_t)n * NCMAX + g] = 1.0f;
        }
    }
}

// ---------------- entry point ----------------
extern "C" void kernel_launch(void* const* d_in, const int* in_sizes, int n_in,
                              void* d_out, int out_size) {
    (void)in_sizes; (void)n_in; (void)out_size;
    const float* f = (const float*)d_in[0];

    cudaFuncSetAttribute(dbscan_kernel,
                         cudaFuncAttributeMaxDynamicSharedMemorySize, SMEM_BYTES);

    transpose_kernel<<<NB * (NPTS / 64), 256>>>(f);
    dbscan_kernel<<<NSM, 1024, SMEM_BYTES>>>();
    offsets_kernel<<<1, NSEG>>>();
    scatter_kernel<<<NB * (NPTS / 128), 256>>>((float*)d_out);
}

// round 9
// speedup vs baseline: 1.9464x; 1.0098x over previous
#include <cuda_runtime.h>
#include <cstdint>

#define NPTS 16384
#define NDIM 64
#define NB   8
#define NSEG (NB * NDIM)
#define EPSF 0.1f
#define MINS 5
#define NCMAX 512
#define FULLM 0xffffffffu
#define NSM 148
#define NBINS 16384

// ---------------- global scratch ----------------
__device__ float    g_xt[(size_t)NB * NDIM * NPTS];
__device__ short    g_lab[(size_t)NB * NDIM * NPTS];
__device__ int      g_ncl[NSEG];
__device__ int      g_off[NSEG];
__device__ unsigned g_ctr;

extern __shared__ unsigned char dsm[];

// ---------------- kernel 0: transpose (B,N,D) -> (B,D,N) ----------------
__global__ void transpose_kernel(const float* __restrict__ f) {
    __shared__ float tile[64][65];
    if (blockIdx.x == 0 && threadIdx.x == 0) g_ctr = 0u;
    int b  = blockIdx.x >> 8;
    int n0 = (blockIdx.x & 255) << 6;
    int tid = threadIdx.x;
    const float* src = f + ((size_t)b * NPTS + n0) * NDIM;
    #pragma unroll
    for (int idx = tid; idx < 64 * 64; idx += 256) {
        int n = idx >> 6, d = idx & 63;
        tile[n][d] = src[idx];
    }
    __syncthreads();
    #pragma unroll
    for (int idx = tid; idx < 64 * 64; idx += 256) {
        int d = idx >> 6, n = idx & 63;
        g_xt[(((size_t)b * NDIM + d) << 14) + n0 + n] = tile[n][d];
    }
}

// ---------------- block scan helpers (1024 threads) ----------------
__device__ __forceinline__ int blkscan_excl_add(int v, int* aux) {
    int lane = threadIdx.x & 31, wid = threadIdx.x >> 5;
    int incl = v;
    #pragma unroll
    for (int o = 1; o < 32; o <<= 1) {
        int u = __shfl_up_sync(FULLM, incl, o);
        if (lane >= o) incl += u;
    }
    if (lane == 31) aux[wid] = incl;
    __syncthreads();
    if (wid == 0) {
        int w = aux[lane];
        #pragma unroll
        for (int o = 1; o < 32; o <<= 1) {
            int u = __shfl_up_sync(FULLM, w, o);
            if (lane >= o) w += u;
        }
        aux[lane] = w;
    }
    __syncthreads();
    int wex = __shfl_up_sync(FULLM, incl, 1);
    if (lane == 0) wex = 0;
    int pre = (wid > 0) ? (wex + aux[wid - 1]) : wex;
    __syncthreads();
    return pre;
}

__device__ __forceinline__ int blkscan_excl_max(int v, int* aux) {
    int lane = threadIdx.x & 31, wid = threadIdx.x >> 5;
    int incl = v;
    #pragma unroll
    for (int o = 1; o < 32; o <<= 1) {
        int u = __shfl_up_sync(FULLM, incl, o);
        if (lane >= o) incl = max(incl, u);
    }
    if (lane == 31) aux[wid] = incl;
    __syncthreads();
    if (wid == 0) {
        int w = aux[lane];
        #pragma unroll
        for (int o = 1; o < 32; o <<= 1) {
            int u = __shfl_up_sync(FULLM, w, o);
            if (lane >= o) w = max(w, u);
        }
        aux[lane] = w;
    }
    __syncthreads();
    int wex = __shfl_up_sync(FULLM, incl, 1);
    if (lane == 0) wex = -1;
    int pre = (wid > 0) ? max(wex, aux[wid - 1]) : wex;
    __syncthreads();
    return pre;
}

__device__ __forceinline__ int blkscan_excl_min_suffix(int v, int* aux) {
    int lane = threadIdx.x & 31, wid = threadIdx.x >> 5;
    int incl = v;
    #pragma unroll
    for (int o = 1; o < 32; o <<= 1) {
        int u = __shfl_down_sync(FULLM, incl, o);
        if (lane < 32 - o) incl = min(incl, u);
    }
    if (lane == 0) aux[wid] = incl;
    __syncthreads();
    if (wid == 0) {
        int w = aux[lane];
        #pragma unroll
        for (int o = 1; o < 32; o <<= 1) {
            int u = __shfl_down_sync(FULLM, w, o);
            if (lane < 32 - o) w = min(w, u);
        }
        aux[lane] = w;
    }
    __syncthreads();
    int wex = __shfl_down_sync(FULLM, incl, 1);
    if (lane == 31) wex = NPTS;
    int pre = (wid < 31) ? min(wex, aux[wid + 1]) : wex;
    __syncthreads();
    return pre;
}

// ---------------- kernel 1: persistent per-(b,d) 1D DBSCAN (bin-sort, 1 atomic pass) ----------------
// smem layout (bytes):
//   [0,      65536)  float xs[16384]
//   [65536,  98304)  u16  ordv[16384]
//   [98304, 131072)  u32  histp[8192] (2x u16)  -> u8 corev[16384] @98304 after scan
//   [131072,163844)  u16  boff[16385]           (dead after phase 3)
//   [114688,147456)  s16  lastc[16384]          (phase 4+, overlaps corev spare + dead boff head)
//   [147456,180224)  s16  nextc[16384]          (phase 6+, overlaps dead boff tail)
//   [180224,212992)  s16  cidv[16384]
//   [212992,213120)  i32  aux[32]
//   [213120,213248)  f32  redmn[32]
//   [213248,213376)  f32  redmx[32]
//   [213376,213388)  s_bd, s_mn, s_mx
#define OFF_ORD   65536
#define OFF_HIST  98304
#define OFF_CORE  98304
#define OFF_LASTC 114688
#define OFF_BOFF  131072
#define OFF_NEXTC 147456
#define OFF_CID   180224
#define OFF_AUX   212992
#define OFF_REDN  213120
#define OFF_REDX  213248
#define OFF_SBD   213376
#define OFF_SMN   213380
#define OFF_SMX   213384
#define SMEM_BYTES 213388

__global__ void __launch_bounds__(1024, 1) dbscan_kernel() {
    float*          xs    = (float*)dsm;
    uint16_t*       ordv  = (uint16_t*)(dsm + OFF_ORD);
    uint32_t*       histp = (uint32_t*)(dsm + OFF_HIST);
    uint16_t*       boff  = (uint16_t*)(dsm + OFF_BOFF);
    unsigned char*  corev = (unsigned char*)(dsm + OFF_CORE);
    short*          lastc = (short*)(dsm + OFF_LASTC);
    short*          nextc = (short*)(dsm + OFF_NEXTC);
    short*          cidv  = (short*)(dsm + OFF_CID);
    int*            aux   = (int*)(dsm + OFF_AUX);
    float*          redmn = (float*)(dsm + OFF_REDN);
    float*          redmx = (float*)(dsm + OFF_REDX);
    int*            s_bd  = (int*)(dsm + OFF_SBD);
    float*          s_mn  = (float*)(dsm + OFF_SMN);
    float*          s_mx  = (float*)(dsm + OFF_SMX);

    int tid  = threadIdx.x;
    int lane = tid & 31;
    int wid  = tid >> 5;
    int base = tid << 4;

    for (;;) {
        if (tid == 0) *s_bd = (int)atomicAdd(&g_ctr, 1u);
        __syncthreads();
        int bd = *s_bd;
        if (bd >= NSEG) return;
        const float* x = g_xt + ((size_t)bd << 14);

        // ---- load 16 values (coalesced) + zero histogram ----
        float v[16];
        #pragma unroll
        for (int q = 0; q < 16; q++) v[q] = x[tid + (q << 10)];
        #pragma unroll 4
        for (int w = tid; w < 8192; w += 1024) histp[w] = 0;

        // ---- block min/max ----
        float mn = v[0], mx = v[0];
        #pragma unroll
        for (int q = 1; q < 16; q++) { mn = fminf(mn, v[q]); mx = fmaxf(mx, v[q]); }
        #pragma unroll
        for (int o = 16; o > 0; o >>= 1) {
            mn = fminf(mn, __shfl_xor_sync(FULLM, mn, o));
            mx = fmaxf(mx, __shfl_xor_sync(FULLM, mx, o));
        }
        if (lane == 0) { redmn[wid] = mn; redmx[wid] = mx; }
        __syncthreads();
        if (wid == 0) {
            mn = redmn[lane]; mx = redmx[lane];
            #pragma unroll
            for (int o = 16; o > 0; o >>= 1) {
                mn = fminf(mn, __shfl_xor_sync(FULLM, mn, o));
                mx = fmaxf(mx, __shfl_xor_sync(FULLM, mx, o));
            }
            if (lane == 0) { *s_mn = mn; *s_mx = mx; }
        }
        __syncthreads();
        mn = *s_mn;
        float range = *s_mx - mn;
        float scale = (range > 0.0f) ? (16383.0f / range) : 0.0f;

        if (range > 0.0f) {
            // ---- histogram WITH rank capture (single atomic pass) ----
            uint32_t rk[8];   // ranks packed: item q in low half, q+8 in high half
            #pragma unroll
            for (int q = 0; q < 8; q++) {
                int b0 = min((int)((v[q] - mn) * scale), NBINS - 1);
                uint32_t o0 = atomicAdd(&histp[b0 >> 1], (b0 & 1) ? 65536u : 1u);
                uint32_t r0 = (b0 & 1) ? (o0 >> 16) : (o0 & 0xffffu);
                int b1 = min((int)((v[q + 8] - mn) * scale), NBINS - 1);
                uint32_t o1 = atomicAdd(&histp[b1 >> 1], (b1 & 1) ? 65536u : 1u);
                uint32_t r1 = (b1 & 1) ? (o1 >> 16) : (o1 & 0xffffu);
                rk[q] = r0 | (r1 << 16);
            }
            __syncthreads();

            // ---- prefix over 16384 bins -> boff (+ sentinel) ----
            {
                int t16 = tid << 4;
                int cnt[16];
                #pragma unroll
                for (int j = 0; j < 8; j++) {
                    uint32_t w = histp[(t16 >> 1) + j];
                    cnt[2 * j]     = (int)(w & 0xffffu);
                    cnt[2 * j + 1] = (int)(w >> 16);
                }
                int tot = 0;
                #pragma unroll
                for (int q = 0; q < 16; q++) tot += cnt[q];
                int bs = blkscan_excl_add(tot, aux);
                #pragma unroll
                for (int q = 0; q < 16; q++) { boff[t16 + q] = (uint16_t)bs; bs += cnt[q]; }
                if (tid == 1023) boff[NBINS] = (uint16_t)NPTS;
            }
            __syncthreads();

            // ---- scatter (no atomics): dst = boff[bin] + rank ----
            #pragma unroll
            for (int q = 0; q < 16; q++) {
                int b = min((int)((v[q] - mn) * scale), NBINS - 1);
                int r = (q < 8) ? (int)(rk[q] & 0xffffu) : (int)(rk[q - 8] >> 16);
                int dst = (int)boff[b] + r;
                xs[dst]   = v[q];
                ordv[dst] = (uint16_t)(tid + (q << 10));
            }
            __syncthreads();

            // ---- cleanup: insertion-sort multi-element bins (hi = boff[b+1]) ----
            #pragma unroll 1
            for (int k = 0; k < 16; k++) {
                int b  = tid + (k << 10);
                int lo = (int)boff[b];
                int hi = (int)boff[b + 1];
                for (int i2 = lo + 1; i2 < hi; i2++) {
                    float kv = xs[i2]; uint16_t pv = ordv[i2];
                    int j = i2 - 1;
                    while (j >= lo && xs[j] > kv) {
                        xs[j + 1] = xs[j]; ordv[j + 1] = ordv[j]; j--;
                    }
                    xs[j + 1] = kv; ordv[j + 1] = pv;
                }
            }
            __syncthreads();

            // ---- phase 3: core test via bin-seeded exact windows ----
            // monotone bin map => searchsorted boundary lies at/after boff[b*];
            // exact float compares finish the job.
            #pragma unroll 2
            for (int q = 0; q < 16; q++) {
                int i = base + q;
                float vv  = xs[i];
                float vhi = vv + EPSF;
                float vlo = vv - EPSF;
                int bh = (int)((vhi - mn) * scale);
                bh = min(max(bh, 0), NBINS - 1);
                int ph = (int)boff[bh];
                while (ph < NPTS && xs[ph] <= vhi) ph++;
                int bl = (int)((vlo - mn) * scale);
                bl = min(max(bl, 0), NBINS - 1);
                int pl = (int)boff[bl];
                while (pl < NPTS && xs[pl] < vlo) pl++;
                corev[i] = (unsigned char)((ph - pl) >= MINS);
            }
        } else {
            // all values equal: sorted trivially; every point is core, one cluster
            #pragma unroll
            for (int q = 0; q < 16; q++) {
                int i = tid + (q << 10);
                xs[i] = v[q]; ordv[i] = (uint16_t)i;
            }
            __syncthreads();
            #pragma unroll
            for (int q = 0; q < 16; q++) corev[base + q] = 1;
        }
        __syncthreads();

        // ---- phase 4: forward inclusive max (core ? i : -1) -> nearest left core ----
        {
            int run = -1;
            #pragma unroll 4
            for (int q = 0; q < 16; q++) {
                int i = base + q;
                int vv = corev[i] ? i : -1;
                if (vv > run) run = vv;
                lastc[i] = (short)run;
            }
            int pre = blkscan_excl_max(run, aux);
            #pragma unroll 4
            for (int q = 0; q < 16; q++) {
                int i = base + q;
                int c = (int)lastc[i];
                if (pre > c) lastc[i] = (short)pre;
            }
        }
        __syncthreads();

        // ---- phase 5: new_cluster + cumsum -> cid ----
        {
            int run = 0;
            #pragma unroll 4
            for (int q = 0; q < 16; q++) {
                int i = base + q;
                int p = (i == 0) ? -1 : (int)lastc[i - 1];
                float pv = (p >= 0) ? xs[p] : -INFINITY;
                int nc = (corev[i] && ((xs[i] - pv) > EPSF)) ? 1 : 0;
                run += nc;
                cidv[i] = (short)run;
            }
            int pre = blkscan_excl_add(run, aux);
            #pragma unroll 4
            for (int q = 0; q < 16; q++) {
                int i = base + q;
                cidv[i] = (short)((int)cidv[i] + pre - 1);
            }
        }
        __syncthreads();

        // ---- phase 6: backward inclusive min (core ? i : NPTS) -> nearest right core ----
        {
            int run = NPTS;
            #pragma unroll 4
            for (int q = 15; q >= 0; q--) {
                int i = base + q;
                int vv = corev[i] ? i : NPTS;
                if (vv < run) run = vv;
                nextc[i] = (short)run;
            }
            int pre = blkscan_excl_min_suffix(run, aux);
            #pragma unroll 4
            for (int q = 0; q < 16; q++) {
                int i = base + q;
                int vv = (int)nextc[i];
                if (pre < vv) nextc[i] = (short)pre;
            }
        }
        __syncthreads();

        // ---- phase 7: labels -> unsort to g_lab; write ncl ----
        #pragma unroll 2
        for (int q = 0; q < 16; q++) {
            int i = base + q;
            int lab;
            if (corev[i]) {
                lab = (int)cidv[i];
            } else {
                int lc = (int)lastc[i], rc = (int)nextc[i];
                float lv = (lc >= 0)   ? xs[lc] : -INFINITY;
                float rv = (rc < NPTS) ? xs[rc] :  INFINITY;
                float dl = xs[i] - lv;
                float dr = rv - xs[i];
                float mmn = dl < dr ? dl : dr;
                if (mmn <= EPSF) lab = (dl <= dr) ? (int)cidv[lc] : (int)cidv[rc];
                else             lab = -1;
            }
            g_lab[((size_t)bd << 14) + ordv[i]] = (short)lab;
            if (i == NPTS - 1) g_ncl[bd] = (int)cidv[i] + 1;
        }
        __syncthreads();
    }
}

// ---------------- kernel 2: offsets ----------------
__global__ void offsets_kernel() {
    __shared__ int s[NSEG];
    int t = threadIdx.x;
    s[t] = g_ncl[t];
    __syncthreads();
    int b = t >> 6, d = t & 63;
    int off = 0;
    for (int j = 0; j < d; j++) off += s[(b << 6) + j];
    g_off[t] = off;
}

// ---------------- kernel 3: fused zero + scatter ----------------
__global__ void scatter_kernel(float* __restrict__ out) {
    __shared__ short labs[64 * 128];
    __shared__ int   offs[64];
    int b  = blockIdx.x >> 7;
    int n0 = (blockIdx.x & 127) << 7;
    int tid = threadIdx.x;
    if (tid < 64) offs[tid] = g_off[(b << 6) + tid];
    for (int idx = tid; idx < 64 * 128; idx += 256) {
        int d = idx >> 7, n = idx & 127;
        labs[idx] = g_lab[(((size_t)(b * NDIM + d)) << 14) + n0 + n];
    }
    __syncthreads();
    float* o = out + (((size_t)b * NPTS) + n0) * NCMAX;
    float4* o4 = (float4*)o;
    float4 z = make_float4(0.f, 0.f, 0.f, 0.f);
    for (int idx = tid; idx < 128 * NCMAX / 4; idx += 256) o4[idx] = z;
    __syncthreads();
    for (int idx = tid; idx < 128 * 64; idx += 256) {
        int n = idx >> 6, d = idx & 63;
        int lab = (int)labs[d * 128 + n];
        if (lab >= 0) {
            int g = lab + offs[d];
            if (g < NCMAX) o[(size_t)n * NCMAX + g] = 1.0f;
        }
    }
}

// ---------------- entry point ----------------
extern "C" void kernel_launch(void* const* d_in, const int* in_sizes, int n_in,
                              void* d_out, int out_size) {
    (void)in_sizes; (void)n_in; (void)out_size;
    const float* f = (const float*)d_in[0];

    cudaFuncSetAttribute(dbscan_kernel,
                         cudaFuncAttributeMaxDynamicSharedMemorySize, SMEM_BYTES);

    transpose_kernel<<<NB * (NPTS / 64), 256>>>(f);
    dbscan_kernel<<<NSM, 1024, SMEM_BYTES>>>();
    offsets_kernel<<<1, NSEG>>>();
    scatter_kernel<<<NB * (NPTS / 128), 256>>>((float*)d_out);
}

// round 10
// speedup vs baseline: 2.5880x; 1.3297x over previous
#include <cuda_runtime.h>
#include <cstdint>

#define NPTS 16384
#define NDIM 64
#define NB   8
#define NSEG (NB * NDIM)
#define EPSF 0.1f
#define MINS 5
#define NCMAX 512
#define FULLM 0xffffffffu
#define NSM 148
#define NBINS 8192

// ---------------- global scratch ----------------
__device__ float    g_xt[(size_t)NB * NDIM * NPTS];
__device__ short    g_lab[(size_t)NB * NDIM * NPTS];
__device__ int      g_ncl[NSEG];
__device__ int      g_off[NSEG];
__device__ unsigned g_ctr;

extern __shared__ unsigned char dsm[];

// ---------------- kernel 0: transpose (B,N,D) -> (B,D,N) ----------------
__global__ void transpose_kernel(const float* __restrict__ f) {
    __shared__ float tile[64][65];
    if (blockIdx.x == 0 && threadIdx.x == 0) g_ctr = 0u;
    int b  = blockIdx.x >> 8;
    int n0 = (blockIdx.x & 255) << 6;
    int tid = threadIdx.x;
    const float* src = f + ((size_t)b * NPTS + n0) * NDIM;
    #pragma unroll
    for (int idx = tid; idx < 64 * 64; idx += 256) {
        int n = idx >> 6, d = idx & 63;
        tile[n][d] = src[idx];
    }
    __syncthreads();
    #pragma unroll
    for (int idx = tid; idx < 64 * 64; idx += 256) {
        int d = idx >> 6, n = idx & 63;
        g_xt[(((size_t)b * NDIM + d) << 14) + n0 + n] = tile[n][d];
    }
}

// ---------------- block scans for 512 threads (16 warps) ----------------
__device__ __forceinline__ int scan_add_512(int v, int* aux) {
    int lane = threadIdx.x & 31, wid = threadIdx.x >> 5;
    int incl = v;
    #pragma unroll
    for (int o = 1; o < 32; o <<= 1) {
        int u = __shfl_up_sync(FULLM, incl, o);
        if (lane >= o) incl += u;
    }
    if (lane == 31) aux[wid] = incl;
    __syncthreads();
    if (wid == 0 && lane < 16) {
        int w = aux[lane];
        #pragma unroll
        for (int o = 1; o < 16; o <<= 1) {
            int u = __shfl_up_sync(0xffffu, w, o);
            if (lane >= o) w += u;
        }
        aux[lane] = w;
    }
    __syncthreads();
    int wex = __shfl_up_sync(FULLM, incl, 1);
    if (lane == 0) wex = 0;
    int pre = (wid > 0) ? (wex + aux[wid - 1]) : wex;
    __syncthreads();
    return pre;
}

__device__ __forceinline__ float scan_fmax_excl_512(float v, float* faux) {
    int lane = threadIdx.x & 31, wid = threadIdx.x >> 5;
    float incl = v;
    #pragma unroll
    for (int o = 1; o < 32; o <<= 1) {
        float u = __shfl_up_sync(FULLM, incl, o);
        if (lane >= o) incl = fmaxf(incl, u);
    }
    if (lane == 31) faux[wid] = incl;
    __syncthreads();
    if (wid == 0 && lane < 16) {
        float w = faux[lane];
        #pragma unroll
        for (int o = 1; o < 16; o <<= 1) {
            float u = __shfl_up_sync(0xffffu, w, o);
            if (lane >= o) w = fmaxf(w, u);
        }
        faux[lane] = w;
    }
    __syncthreads();
    float wex = __shfl_up_sync(FULLM, incl, 1);
    if (lane == 0) wex = -INFINITY;
    float pre = (wid > 0) ? fmaxf(wex, faux[wid - 1]) : wex;
    __syncthreads();
    return pre;
}

__device__ __forceinline__ float scan_fmin_sufx_512(float v, float* faux) {
    int lane = threadIdx.x & 31, wid = threadIdx.x >> 5;
    float incl = v;
    #pragma unroll
    for (int o = 1; o < 32; o <<= 1) {
        float u = __shfl_down_sync(FULLM, incl, o);
        if (lane < 32 - o) incl = fminf(incl, u);
    }
    if (lane == 0) faux[wid] = incl;
    __syncthreads();
    if (wid == 0 && lane < 16) {
        float w = faux[lane];
        #pragma unroll
        for (int o = 1; o < 16; o <<= 1) {
            float u = __shfl_down_sync(0xffffu, w, o);
            if (lane < 16 - o) w = fminf(w, u);
        }
        faux[lane] = w;
    }
    __syncthreads();
    float wex = __shfl_down_sync(FULLM, incl, 1);
    if (lane == 31) wex = INFINITY;
    float pre = (wid < 15) ? fminf(wex, faux[wid + 1]) : wex;
    __syncthreads();
    return pre;
}

// ---------------- kernel 1: persistent per-(b,d) DBSCAN, 512 thr, 2 CTA/SM ----------------
// smem (bytes):
//   [0,      65536)  float xs[16384]      (sorted values)
//   [65536,  98304)  u16  ordv[16384]     (original index)
//   [98304, 114692)  u16  hist/boff[8194] (in-place: counts -> offsets; [8192]=sentinel)
//   [114692,114756)  i32  aux[16]
//   [114756,114820)  f32  faux[16]
//   [114820,114884)  f32  redmn[16]
//   [114884,114948)  f32  redmx[16]
//   [114948,114960)  s_bd, s_mn, s_mx
#define OFF_ORD  65536
#define OFF_HB   98304
#define OFF_AUX  114692
#define OFF_FAUX 114756
#define OFF_REDN 114820
#define OFF_REDX 114884
#define OFF_SBD  114948
#define OFF_SMN  114952
#define OFF_SMX  114956
#define SMEM_BYTES 114960

__global__ void __launch_bounds__(512, 2) dbscan_kernel() {
    float*     xs    = (float*)dsm;
    uint16_t*  ordv  = (uint16_t*)(dsm + OFF_ORD);
    uint32_t*  histp = (uint32_t*)(dsm + OFF_HB);
    uint16_t*  boff  = (uint16_t*)(dsm + OFF_HB);
    int*       aux   = (int*)(dsm + OFF_AUX);
    float*     faux  = (float*)(dsm + OFF_FAUX);
    float*     redmn = (float*)(dsm + OFF_REDN);
    float*     redmx = (float*)(dsm + OFF_REDX);
    int*       s_bd  = (int*)(dsm + OFF_SBD);
    float*     s_mn  = (float*)(dsm + OFF_SMN);
    float*     s_mx  = (float*)(dsm + OFF_SMX);

    int tid  = threadIdx.x;
    int lane = tid & 31;
    int wid  = tid >> 5;

    for (;;) {
        if (tid == 0) *s_bd = (int)atomicAdd(&g_ctr, 1u);
        __syncthreads();
        int bd = *s_bd;
        if (bd >= NSEG) return;
        const float4* xv = (const float4*)(g_xt + ((size_t)bd << 14));
        size_t gb = (size_t)bd << 14;

        // ---- zero hist + local min/max (one fused region, 2 syncs) ----
        #pragma unroll
        for (int j = tid; j < 4097; j += 512) histp[j] = 0;
        float mn = INFINITY, mx = -INFINITY;
        #pragma unroll
        for (int c = 0; c < 8; c++) {
            float4 f = xv[(c << 9) + tid];
            mn = fminf(mn, fminf(fminf(f.x, f.y), fminf(f.z, f.w)));
            mx = fmaxf(mx, fmaxf(fmaxf(f.x, f.y), fmaxf(f.z, f.w)));
        }
        #pragma unroll
        for (int o = 16; o > 0; o >>= 1) {
            mn = fminf(mn, __shfl_xor_sync(FULLM, mn, o));
            mx = fmaxf(mx, __shfl_xor_sync(FULLM, mx, o));
        }
        if (lane == 0) { redmn[wid] = mn; redmx[wid] = mx; }
        __syncthreads();
        if (wid == 0 && lane < 16) {
            mn = redmn[lane]; mx = redmx[lane];
            #pragma unroll
            for (int o = 8; o > 0; o >>= 1) {
                mn = fminf(mn, __shfl_xor_sync(0xffffu, mn, o));
                mx = fmaxf(mx, __shfl_xor_sync(0xffffu, mx, o));
            }
            if (lane == 0) { *s_mn = mn; *s_mx = mx; }
        }
        __syncthreads();
        mn = *s_mn;
        float range = *s_mx - mn;

        if (range > 0.0f) {                       // uniform branch
            float scale = 8191.0f / range;

            // ---- histogram with rank capture (single atomic pass) ----
            uint32_t rk[16];
            #pragma unroll
            for (int c = 0; c < 8; c++) {
                float4 f = xv[(c << 9) + tid];
                int b0 = min((int)((f.x - mn) * scale), NBINS - 1);
                uint32_t o0 = atomicAdd(&histp[b0 >> 1], (b0 & 1) ? 65536u : 1u);
                uint32_t r0 = (b0 & 1) ? (o0 >> 16) : (o0 & 0xffffu);
                int b1 = min((int)((f.y - mn) * scale), NBINS - 1);
                uint32_t o1 = atomicAdd(&histp[b1 >> 1], (b1 & 1) ? 65536u : 1u);
                uint32_t r1 = (b1 & 1) ? (o1 >> 16) : (o1 & 0xffffu);
                int b2 = min((int)((f.z - mn) * scale), NBINS - 1);
                uint32_t o2 = atomicAdd(&histp[b2 >> 1], (b2 & 1) ? 65536u : 1u);
                uint32_t r2 = (b2 & 1) ? (o2 >> 16) : (o2 & 0xffffu);
                int b3 = min((int)((f.w - mn) * scale), NBINS - 1);
                uint32_t o3 = atomicAdd(&histp[b3 >> 1], (b3 & 1) ? 65536u : 1u);
                uint32_t r3 = (b3 & 1) ? (o3 >> 16) : (o3 & 0xffffu);
                rk[c * 2]     = r0 | (r1 << 16);
                rk[c * 2 + 1] = r2 | (r3 << 16);
            }
            __syncthreads();

            // ---- in-place prefix: counts -> offsets (16 bins/thread) ----
            {
                int t16 = tid << 4;
                int cnt[16];
                #pragma unroll
                for (int j = 0; j < 8; j++) {
                    uint32_t w = histp[(t16 >> 1) + j];
                    cnt[2 * j]     = (int)(w & 0xffffu);
                    cnt[2 * j + 1] = (int)(w >> 16);
                }
                int tot = 0;
                #pragma unroll
                for (int q = 0; q < 16; q++) tot += cnt[q];
                int bs = scan_add_512(tot, aux);
                #pragma unroll
                for (int q = 0; q < 16; q++) { boff[t16 + q] = (uint16_t)bs; bs += cnt[q]; }
                if (tid == 511) boff[NBINS] = (uint16_t)NPTS;
            }
            __syncthreads();

            // ---- scatter: dst = boff[bin] + rank ----
            #pragma unroll
            for (int c = 0; c < 8; c++) {
                float4 f = xv[(c << 9) + tid];
                int orig = ((c << 9) + tid) << 2;
                int b0 = min((int)((f.x - mn) * scale), NBINS - 1);
                int d0 = (int)boff[b0] + (int)(rk[c * 2] & 0xffffu);
                xs[d0] = f.x; ordv[d0] = (uint16_t)orig;
                int b1 = min((int)((f.y - mn) * scale), NBINS - 1);
                int d1 = (int)boff[b1] + (int)(rk[c * 2] >> 16);
                xs[d1] = f.y; ordv[d1] = (uint16_t)(orig + 1);
                int b2 = min((int)((f.z - mn) * scale), NBINS - 1);
                int d2 = (int)boff[b2] + (int)(rk[c * 2 + 1] & 0xffffu);
                xs[d2] = f.z; ordv[d2] = (uint16_t)(orig + 2);
                int b3 = min((int)((f.w - mn) * scale), NBINS - 1);
                int d3 = (int)boff[b3] + (int)(rk[c * 2 + 1] >> 16);
                xs[d3] = f.w; ordv[d3] = (uint16_t)(orig + 3);
            }
            __syncthreads();

            // ---- cleanup: insertion-sort multi-element bins (interleaved) ----
            #pragma unroll 1
            for (int k = 0; k < 16; k++) {
                int b  = tid + (k << 9);
                int lo = (int)boff[b];
                int hi = (int)boff[b + 1];
                for (int i2 = lo + 1; i2 < hi; i2++) {
                    float kv = xs[i2]; uint16_t pv = ordv[i2];
                    int j = i2 - 1;
                    while (j >= lo && xs[j] > kv) {
                        xs[j + 1] = xs[j]; ordv[j + 1] = ordv[j]; j--;
                    }
                    xs[j + 1] = kv; ordv[j + 1] = pv;
                }
            }
            __syncthreads();

            // ---- register cache: v2[32] via vectorized LDS ----
            int base2 = tid << 5;
            float v2[32];
            #pragma unroll
            for (int k = 0; k < 8; k++) {
                float4 f = ((const float4*)xs)[(tid << 3) + k];
                v2[4 * k] = f.x; v2[4 * k + 1] = f.y;
                v2[4 * k + 2] = f.z; v2[4 * k + 3] = f.w;
            }

            // ---- core test: bin-seeded monotone windows (exact searchsorted) ----
            unsigned coremask = 0;
            float Lsum = -INFINITY, Rsum = INFINITY;
            {
                float vhi = v2[0] + EPSF, vlo = v2[0] - EPSF;
                int bh = min((int)((vhi - mn) * scale), NBINS - 1);
                int ph = (int)boff[bh];
                while (ph < NPTS && xs[ph] <= vhi) ph++;
                int bl = max(min((int)((vlo - mn) * scale), NBINS - 1), 0);
                int pl = (int)boff[bl];
                while (pl < NPTS && xs[pl] < vlo) pl++;
                #pragma unroll
                for (int q = 0; q < 32; q++) {
                    if (q) {
                        vhi = v2[q] + EPSF; vlo = v2[q] - EPSF;
                        while (ph < NPTS && xs[ph] <= vhi) ph++;
                        while (pl < NPTS && xs[pl] < vlo) pl++;
                    }
                    if (ph - pl >= MINS) {
                        coremask |= 1u << q;
                        if (Rsum == INFINITY) Rsum = v2[q];
                        Lsum = v2[q];
                    }
                }
            }

            // ---- scans: L_in (fwd max), S_in (fwd add), R_in (bwd min) ----
            float L_in = scan_fmax_excl_512(Lsum, faux);
            unsigned startmask = 0;
            {
                float run = L_in;
                #pragma unroll
                for (int q = 0; q < 32; q++) {
                    if (coremask & (1u << q)) {
                        if (v2[q] - run > EPSF) startmask |= 1u << q;
                        run = v2[q];
                    }
                }
            }
            int Ssum = __popc(startmask);
            int S_in = scan_add_512(Ssum, aux);
            float R_in = scan_fmin_sufx_512(Rsum, faux);

            // ---- labels (register-resident), write to g_lab via ordv ----
            {
                float runL = L_in;
                int S_run = S_in;
                #pragma unroll
                for (int k = 0; k < 8; k++) {
                    uint2 ow = ((const uint2*)ordv)[(tid << 3) + k];
                    unsigned o0 = ow.x & 0xffffu, o1 = ow.x >> 16;
                    unsigned o2 = ow.y & 0xffffu, o3 = ow.y >> 16;
                    #pragma unroll
                    for (int j = 0; j < 4; j++) {
                        int q = 4 * k + j;
                        unsigned bit = 1u << q;
                        int lab;
                        if (coremask & bit) {
                            if (startmask & bit) S_run++;
                            runL = v2[q];
                            lab = S_run - 1;
                        } else {
                            float leftv = runL;
                            unsigned mhi = (q < 31) ? (coremask >> (q + 1)) : 0u;
                            float rightv = mhi ? xs[base2 + q + __ffs(mhi)] : R_in;
                            float dl = v2[q] - leftv;
                            float dr = rightv - v2[q];
                            float mmn = fminf(dl, dr);
                            if (mmn <= EPSF)
                                lab = (dl <= dr) ? (S_run - 1)
                                    : (S_run - 1 + (((rightv - leftv) > EPSF) ? 1 : 0));
                            else lab = -1;
                        }
                        unsigned oo = (j == 0) ? o0 : (j == 1) ? o1 : (j == 2) ? o2 : o3;
                        g_lab[gb + oo] = (short)lab;
                    }
                }
                if (tid == 511) g_ncl[bd] = S_in + Ssum;
            }
        } else {
            // all values equal: all core, one cluster, labels all 0
            #pragma unroll
            for (int c = 0; c < 8; c++) {
                int o = ((c << 9) + tid) << 2;
                *((uint64_t*)&g_lab[gb + o]) = 0ull;
            }
            if (tid == 0) g_ncl[bd] = 1;
        }
        __syncthreads();
    }
}

// ---------------- kernel 2: offsets ----------------
__global__ void offsets_kernel() {
    __shared__ int s[NSEG];
    int t = threadIdx.x;
    s[t] = g_ncl[t];
    __syncthreads();
    int b = t >> 6, d = t & 63;
    int off = 0;
    for (int j = 0; j < d; j++) off += s[(b << 6) + j];
    g_off[t] = off;
}

// ---------------- kernel 3: fused zero + scatter ----------------
__global__ void scatter_kernel(float* __restrict__ out) {
    __shared__ short labs[64 * 128];
    __shared__ int   offs[64];
    int b  = blockIdx.x >> 7;
    int n0 = (blockIdx.x & 127) << 7;
    int tid = threadIdx.x;
    if (tid < 64) offs[tid] = g_off[(b << 6) + tid];
    for (int idx = tid; idx < 64 * 128; idx += 256) {
        int d = idx >> 7, n = idx & 127;
        labs[idx] = g_lab[(((size_t)(b * NDIM + d)) << 14) + n0 + n];
    }
    __syncthreads();
    float* o = out + (((size_t)b * NPTS) + n0) * NCMAX;
    float4* o4 = (float4*)o;
    float4 z = make_float4(0.f, 0.f, 0.f, 0.f);
    for (int idx = tid; idx < 128 * NCMAX / 4; idx += 256) o4[idx] = z;
    __syncthreads();
    for (int idx = tid; idx < 128 * 64; idx += 256) {
        int n = idx >> 6, d = idx & 63;
        int lab = (int)labs[d * 128 + n];
        if (lab >= 0) {
            int g = lab + offs[d];
            if (g < NCMAX) o[(size_t)n * NCMAX + g] = 1.0f;
        }
    }
}

// ---------------- entry point ----------------
extern "C" void kernel_launch(void* const* d_in, const int* in_sizes, int n_in,
                              void* d_out, int out_size) {
    (void)in_sizes; (void)n_in; (void)out_size;
    const float* f = (const float*)d_in[0];

    cudaFuncSetAttribute(dbscan_kernel,
                         cudaFuncAttributeMaxDynamicSharedMemorySize, SMEM_BYTES);

    transpose_kernel<<<NB * (NPTS / 64), 256>>>(f);
    dbscan_kernel<<<NSM * 2, 512, SMEM_BYTES>>>();
    offsets_kernel<<<1, NSEG>>>();
    scatter_kernel<<<NB * (NPTS / 128), 256>>>((float*)d_out);
}